// round 17
// baseline (speedup 1.0000x reference)
#include <cuda_runtime.h>
#include <cuda_fp16.h>
#include <cstdint>
#include <math.h>

#define BDIM 4096
#define DDIM 2048
#define KDIM 2048

// ---------------- device scratch ----------------
// g_flags is monotone-correct across replays: zero-initialized at load; a set
// flag only routes extra inputs through the (mathematically general) slow path.
__device__ int      g_flags[2];            // [0] mem0 nonzero, [1] out0 nonzero
__device__ unsigned g_barcnt = 0;          // software grid barrier state
__device__ unsigned g_bargen = 0;
__device__ float  g_preA[BDIM * DDIM];
__device__ float  g_preB[BDIM * DDIM];
__device__ __half g_ax  [BDIM * KDIM];
__device__ __half g_ay  [BDIM * KDIM];     // out0 fp16
__device__ __half g_az  [BDIM * KDIM];     // mem0 fp16
__device__ __half g_au  [BDIM * KDIM];     // sigmoid(preC)*mem0 fp16
__device__ __half g_w0  [DDIM * KDIM];
__device__ __half g_w1  [DDIM * KDIM];
__device__ __half g_w2  [DDIM * KDIM];
__device__ __half g_w3  [DDIM * KDIM];
__device__ __half g_w4  [DDIM * KDIM];
__device__ __half g_w5  [DDIM * KDIM];
__device__ __half g_w6  [DDIM * KDIM];

// one descriptor for the whole pipeline
struct MegaDesc {
    // phase 0: ungated prep
    const float4* px;   uint2* pax;
    const float4* pmem; const float4* pout;
    const float4* pwi;  uint2* pw0;
    const float4* pwg;  uint2* pw1;
    // phase 1: dual GEMM
    const __half* A;  const __half* W0;  const __half* W1;
    float* preA; float* preB;
    const float* bA0; const float* bA1;
    const float* bB0; const float* bB1; const float* bB2;
    float* outp; const float* bdec;
    // phase 2: slow path
    const float4* csrc[9];
    uint2*        cdst[9];
    int           cn4[9];
    int           cfs[9];
    const __half* A2[3][3];
    const __half* W2[3][3];
    int           pfs2[3][3];
    int           np2[3];
    float*        C2[3];
    const float*  bb0[3];
    const float*  bb1[3];
    const float*  bb2[3];
    int           sfs2[3];
    int           epi2[3];
    const __half* Adec;
    const __half* Wdec;
    const float*  mem0;
    __half*       aup;
};

__device__ __forceinline__ float sigmoidf_(float v) { return 1.0f / (1.0f + expf(-v)); }

__device__ __forceinline__ uint32_t smem_to_u32(const void* p) {
    uint32_t a;
    asm("{ .reg .u64 t; cvta.to.shared.u64 t, %1; cvt.u32.u64 %0, t; }" : "=r"(a) : "l"(p));
    return a;
}

__device__ __forceinline__ void cp16(uint32_t dst, const void* src) {
    asm volatile("cp.async.cg.shared.global [%0], [%1], 16;" :: "r"(dst), "l"(src) : "memory");
}
#define CP_COMMIT() asm volatile("cp.async.commit_group;" ::: "memory")

__device__ __forceinline__ void ldm_x4(uint32_t& r0, uint32_t& r1, uint32_t& r2, uint32_t& r3,
                                       uint32_t addr) {
    asm volatile("ldmatrix.sync.aligned.m8n8.x4.shared.b16 {%0,%1,%2,%3}, [%4];"
                 : "=r"(r0), "=r"(r1), "=r"(r2), "=r"(r3) : "r"(addr));
}

__device__ __forceinline__ void mma_fp16(float* c, const uint32_t* a, const uint32_t* b) {
    asm volatile("mma.sync.aligned.m16n8k16.row.col.f32.f16.f16.f32 "
                 "{%0,%1,%2,%3}, {%4,%5,%6,%7}, {%8,%9}, {%0,%1,%2,%3};"
                 : "+f"(c[0]), "+f"(c[1]), "+f"(c[2]), "+f"(c[3])
                 : "r"(a[0]), "r"(a[1]), "r"(a[2]), "r"(a[3]), "r"(b[0]), "r"(b[1]));
}

__device__ __forceinline__ bool flag_ok(int fs) {
    if (fs == 0) return true;
    if (fs == 4) return (g_flags[0] | g_flags[1]) != 0;
    if (fs == 5) return (g_flags[1] != 0) && (g_flags[0] == 0);
    if ((fs & 1) && g_flags[0] == 0) return false;
    if ((fs & 2) && g_flags[1] == 0) return false;
    return true;
}

// replay-safe software grid barrier (all CTAs resident: grid=296, 2 CTAs/SM)
__device__ __forceinline__ void grid_barrier(unsigned nblocks) {
    __syncthreads();
    if (threadIdx.x == 0) {
        volatile unsigned* vg = &g_bargen;
        unsigned gen = *vg;
        __threadfence();
        if (atomicAdd(&g_barcnt, 1u) == nblocks - 1u) {
            g_barcnt = 0;
            __threadfence();
            atomicAdd(&g_bargen, 1u);
        } else {
            while (*vg == gen) { }
        }
        __threadfence();
    }
    __syncthreads();
}

// ================= shared tiling constants =================
#define BK 64
#define CHUNKS (KDIM / BK)
#define STRB 144
#define NSTAGE 3

// slow-path tile: 128x128
#define CTAM 128
#define CTAN 128
#define A_BYTES (CTAM * STRB)
#define B_BYTES (CTAN * STRB)
#define STAGE_BYTES (A_BYTES + B_BYTES)
#define GEMM_SMEM (NSTAGE * STAGE_BYTES)    // 110592

// fast-path dual tile: 128x64
#define DCTAM 128
#define DCTAN 64
#define D_A_BYTES (DCTAM * STRB)            // 18432
#define D_W_BYTES (DCTAN * STRB)            // 9216
#define D_STAGE (D_A_BYTES + 2 * D_W_BYTES) // 36864  (NSTAGE*D_STAGE == GEMM_SMEM)

// ---------------- tile core (slow path, 128x128, multi-pair) -----------------
__device__ void gemm_tile(uint32_t sb0, int tid, int bm, int bn,
                          int npairs, const __half* const* Ap,
                          const __half* const* Wp, const int* pfs,
                          float c[4][4][4])
{
    const int lane = tid & 31;
    const int wid = tid >> 5;
    const int wm = wid & 1;
    const int wn = wid >> 1;
    const uint32_t a_row = (uint32_t)(wm * 64 + (lane & 15));
    const uint32_t a_kb  = (uint32_t)((lane >> 4) * 16);
    const uint32_t b_row = (uint32_t)(wn * 32 + (lane & 7) + ((lane & 16) ? 8 : 0));
    const uint32_t b_kb  = (uint32_t)((lane & 8) ? 16 : 0);

    for (int p = 0; p < npairs; p++) {
        if (!flag_ok(pfs[p])) continue;
        const __half* __restrict__ A = Ap[p];
        const __half* __restrict__ W = Wp[p];

        auto load_chunk = [&](int stage, int kt) {
            const uint32_t sb = sb0 + (uint32_t)stage * STAGE_BYTES;
            #pragma unroll
            for (int i = 0; i < 4; i++) {
                int gr = tid + i * 256;
                int row = gr >> 3, c8 = gr & 7;
                cp16(sb + (uint32_t)(row * STRB + c8 * 16),
                     A + (size_t)(bm + row) * KDIM + kt + c8 * 8);
            }
            #pragma unroll
            for (int i = 0; i < 4; i++) {
                int gr = tid + i * 256;
                int row = gr >> 3, c8 = gr & 7;
                cp16(sb + (uint32_t)(A_BYTES + row * STRB + c8 * 16),
                     W + (size_t)(bn + row) * KDIM + kt + c8 * 8);
            }
            CP_COMMIT();
        };

        load_chunk(0, 0);
        load_chunk(1, BK);

        int stage = 0;
        for (int ch = 0; ch < CHUNKS; ch++) {
            if (ch + 2 < CHUNKS) {
                int ns = stage + 2; if (ns >= NSTAGE) ns -= NSTAGE;
                load_chunk(ns, (ch + 2) * BK);
                asm volatile("cp.async.wait_group 2;" ::: "memory");
            } else if (ch + 1 < CHUNKS) {
                asm volatile("cp.async.wait_group 1;" ::: "memory");
            } else {
                asm volatile("cp.async.wait_group 0;" ::: "memory");
            }
            __syncthreads();

            const uint32_t As = sb0 + (uint32_t)stage * STAGE_BYTES;
            const uint32_t Bs = As + A_BYTES;

            #pragma unroll
            for (int s = 0; s < 4; s++) {
                const uint32_t kb = (uint32_t)(s * 32);
                uint32_t a[4][4];
                #pragma unroll
                for (int mf = 0; mf < 4; mf++)
                    ldm_x4(a[mf][0], a[mf][1], a[mf][2], a[mf][3],
                           As + (a_row + mf * 16) * STRB + kb + a_kb);
                uint32_t b[4][2];
                #pragma unroll
                for (int nh = 0; nh < 2; nh++) {
                    uint32_t r0, r1, r2, r3;
                    ldm_x4(r0, r1, r2, r3, Bs + (b_row + nh * 16) * STRB + kb + b_kb);
                    b[2 * nh][0] = r0;      b[2 * nh][1] = r1;
                    b[2 * nh + 1][0] = r2;  b[2 * nh + 1][1] = r3;
                }
                #pragma unroll
                for (int mf = 0; mf < 4; mf++)
                    #pragma unroll
                    for (int nf = 0; nf < 4; nf++)
                        mma_fp16(c[mf][nf], a[mf], b[nf]);
            }
            __syncthreads();
            if (++stage >= NSTAGE) stage = 0;
        }
    }
}

// ---------------- dual tile core (fast path, 128x64, two outputs) ------------
__device__ void dual_tile(const MegaDesc& md, uint32_t sb0, int tid, int bm, int bn)
{
    const int wid = tid >> 5;
    const int lane = tid & 31;
    const int g = lane >> 2;
    const int t = lane & 3;
    const int wm = wid & 1;
    const int wn = wid >> 1;

    float cA[4][2][4], cB[4][2][4];
    #pragma unroll
    for (int i = 0; i < 4; i++)
        #pragma unroll
        for (int j = 0; j < 2; j++)
            #pragma unroll
            for (int q = 0; q < 4; q++) { cA[i][j][q] = 0.0f; cB[i][j][q] = 0.0f; }

    const uint32_t a_row = (uint32_t)(wm * 64 + (lane & 15));
    const uint32_t a_kb  = (uint32_t)((lane >> 4) * 16);
    const uint32_t b_row = (uint32_t)(wn * 16 + (lane & 7) + ((lane & 16) ? 8 : 0));
    const uint32_t b_kb  = (uint32_t)((lane & 8) ? 16 : 0);

    const __half* __restrict__ A  = md.A;
    const __half* __restrict__ W0 = md.W0;
    const __half* __restrict__ W1 = md.W1;

    auto load_chunk = [&](int stage, int kt) {
        const uint32_t sb = sb0 + (uint32_t)stage * D_STAGE;
        #pragma unroll
        for (int i = 0; i < 4; i++) {
            int gr = tid + i * 256;
            int row = gr >> 3, c8 = gr & 7;
            cp16(sb + (uint32_t)(row * STRB + c8 * 16),
                 A + (size_t)(bm + row) * KDIM + kt + c8 * 8);
        }
        #pragma unroll
        for (int i = 0; i < 2; i++) {
            int gr = tid + i * 256;
            int row = gr >> 3, c8 = gr & 7;
            cp16(sb + (uint32_t)(D_A_BYTES + row * STRB + c8 * 16),
                 W0 + (size_t)(bn + row) * KDIM + kt + c8 * 8);
        }
        #pragma unroll
        for (int i = 0; i < 2; i++) {
            int gr = tid + i * 256;
            int row = gr >> 3, c8 = gr & 7;
            cp16(sb + (uint32_t)(D_A_BYTES + D_W_BYTES + row * STRB + c8 * 16),
                 W1 + (size_t)(bn + row) * KDIM + kt + c8 * 8);
        }
        CP_COMMIT();
    };

    load_chunk(0, 0);
    load_chunk(1, BK);

    int stage = 0;
    for (int ch = 0; ch < CHUNKS; ch++) {
        if (ch + 2 < CHUNKS) {
            int ns = stage + 2; if (ns >= NSTAGE) ns -= NSTAGE;
            load_chunk(ns, (ch + 2) * BK);
            asm volatile("cp.async.wait_group 2;" ::: "memory");
        } else if (ch + 1 < CHUNKS) {
            asm volatile("cp.async.wait_group 1;" ::: "memory");
        } else {
            asm volatile("cp.async.wait_group 0;" ::: "memory");
        }
        __syncthreads();

        const uint32_t As  = sb0 + (uint32_t)stage * D_STAGE;
        const uint32_t Bs0 = As + D_A_BYTES;
        const uint32_t Bs1 = Bs0 + D_W_BYTES;

        #pragma unroll
        for (int s = 0; s < 4; s++) {
            const uint32_t kb = (uint32_t)(s * 32);
            uint32_t a[4][4];
            #pragma unroll
            for (int mf = 0; mf < 4; mf++)
                ldm_x4(a[mf][0], a[mf][1], a[mf][2], a[mf][3],
                       As + (a_row + mf * 16) * STRB + kb + a_kb);
            uint32_t b0[2][2], b1[2][2];
            {
                uint32_t r0, r1, r2, r3;
                ldm_x4(r0, r1, r2, r3, Bs0 + b_row * STRB + kb + b_kb);
                b0[0][0] = r0; b0[0][1] = r1; b0[1][0] = r2; b0[1][1] = r3;
                ldm_x4(r0, r1, r2, r3, Bs1 + b_row * STRB + kb + b_kb);
                b1[0][0] = r0; b1[0][1] = r1; b1[1][0] = r2; b1[1][1] = r3;
            }
            #pragma unroll
            for (int mf = 0; mf < 4; mf++)
                #pragma unroll
                for (int nf = 0; nf < 2; nf++) {
                    mma_fp16(cA[mf][nf], a[mf], b0[nf]);
                    mma_fp16(cB[mf][nf], a[mf], b1[nf]);
                }
        }
        __syncthreads();
        if (++stage >= NSTAGE) stage = 0;
    }

    // ---- fused epilogue ----
    const bool slow = (g_flags[0] | g_flags[1]) != 0;
    #pragma unroll
    for (int nf = 0; nf < 2; nf++) {
        const int col = bn + wn * 16 + nf * 8 + 2 * t;
        const float bsA0 = md.bA0[col] + md.bA1[col];
        const float bsA1 = md.bA0[col + 1] + md.bA1[col + 1];
        const float bsB0 = md.bB0[col] + md.bB1[col] + md.bB2[col];
        const float bsB1 = md.bB0[col + 1] + md.bB1[col + 1] + md.bB2[col + 1];
        const float d0 = md.bdec[col], d1 = md.bdec[col + 1];
        #pragma unroll
        for (int mf = 0; mf < 4; mf++) {
            const int r = bm + wm * 64 + mf * 16 + g;
            float2 va0 = make_float2(cA[mf][nf][0] + bsA0, cA[mf][nf][1] + bsA1);
            float2 va1 = make_float2(cA[mf][nf][2] + bsA0, cA[mf][nf][3] + bsA1);
            float2 vb0 = make_float2(cB[mf][nf][0] + bsB0, cB[mf][nf][1] + bsB1);
            float2 vb1 = make_float2(cB[mf][nf][2] + bsB0, cB[mf][nf][3] + bsB1);
            if (slow) {
                *(float2*)(md.preA + (size_t)r * DDIM + col) = va0;
                *(float2*)(md.preA + (size_t)(r + 8) * DDIM + col) = va1;
                *(float2*)(md.preB + (size_t)r * DDIM + col) = vb0;
                *(float2*)(md.preB + (size_t)(r + 8) * DDIM + col) = vb1;
            } else {
                float2 o0, o1;
                o0.x = d0 + sigmoidf_(va0.x) * sigmoidf_(vb0.x);
                o0.y = d1 + sigmoidf_(va0.y) * sigmoidf_(vb0.y);
                o1.x = d0 + sigmoidf_(va1.x) * sigmoidf_(vb1.x);
                o1.y = d1 + sigmoidf_(va1.y) * sigmoidf_(vb1.y);
                *(float2*)(md.outp + (size_t)r * DDIM + col) = o0;
                *(float2*)(md.outp + (size_t)(r + 8) * DDIM + col) = o1;
            }
        }
    }
}

// ---------------- the single persistent kernel ----------------
__global__ __launch_bounds__(256, 2)
void mega(MegaDesc md)
{
    extern __shared__ char smem[];
    const uint32_t sb0 = smem_to_u32(smem);
    const int tid = threadIdx.x;
    const unsigned nb = gridDim.x;

    // ===== phase 0: ungated prep (conversions 32B-read/16B-write + scans) ====
    {
        const int n8x = (BDIM * KDIM) / 8;
        const float4* __restrict__ src = md.px;
        uint4* __restrict__ dst = (uint4*)md.pax;
        for (int i = blockIdx.x * 256 + tid; i < n8x; i += nb * 256) {
            float4 v0 = src[2 * i];
            float4 v1 = src[2 * i + 1];
            __half2 h0 = __floats2half2_rn(v0.x, v0.y);
            __half2 h1 = __floats2half2_rn(v0.z, v0.w);
            __half2 h2 = __floats2half2_rn(v1.x, v1.y);
            __half2 h3 = __floats2half2_rn(v1.z, v1.w);
            uint4 o;
            o.x = *(uint32_t*)&h0; o.y = *(uint32_t*)&h1;
            o.z = *(uint32_t*)&h2; o.w = *(uint32_t*)&h3;
            dst[i] = o;
        }
    }
    {
        const int n8 = (BDIM * DDIM) / 8;
        bool nzm = false, nzo = false;
        for (int i = blockIdx.x * 256 + tid; i < n8; i += nb * 256) {
            float4 m0 = md.pmem[2 * i];
            float4 m1 = md.pmem[2 * i + 1];
            float4 o0 = md.pout[2 * i];
            float4 o1 = md.pout[2 * i + 1];
            nzm |= (m0.x != 0.0f) | (m0.y != 0.0f) | (m0.z != 0.0f) | (m0.w != 0.0f);
            nzm |= (m1.x != 0.0f) | (m1.y != 0.0f) | (m1.z != 0.0f) | (m1.w != 0.0f);
            nzo |= (o0.x != 0.0f) | (o0.y != 0.0f) | (o0.z != 0.0f) | (o0.w != 0.0f);
            nzo |= (o1.x != 0.0f) | (o1.y != 0.0f) | (o1.z != 0.0f) | (o1.w != 0.0f);
        }
        if (nzm) atomicOr(&g_flags[0], 1);
        if (nzo) atomicOr(&g_flags[1], 1);
    }
    #pragma unroll
    for (int wj = 0; wj < 2; wj++) {
        const int n8w = (DDIM * KDIM) / 8;
        const float4* __restrict__ src = (wj == 0) ? md.pwi : md.pwg;
        uint4* __restrict__ dst = (uint4*)((wj == 0) ? md.pw0 : md.pw1);
        for (int i = blockIdx.x * 256 + tid; i < n8w; i += nb * 256) {
            float4 v0 = src[2 * i];
            float4 v1 = src[2 * i + 1];
            __half2 h0 = __floats2half2_rn(v0.x, v0.y);
            __half2 h1 = __floats2half2_rn(v0.z, v0.w);
            __half2 h2 = __floats2half2_rn(v1.x, v1.y);
            __half2 h3 = __floats2half2_rn(v1.z, v1.w);
            uint4 o;
            o.x = *(uint32_t*)&h0; o.y = *(uint32_t*)&h1;
            o.z = *(uint32_t*)&h2; o.w = *(uint32_t*)&h3;
            dst[i] = o;
        }
    }
    grid_barrier(nb);

    // ===== phase 1: dual GEMM work-loop (1024 tiles of 128x64) =====
    for (int ti = blockIdx.x; ti < 1024; ti += (int)nb) {
        const int bm = (ti >> 5) * DCTAM;
        const int bn = (ti & 31) * DCTAN;
        dual_tile(md, sb0, tid, bm, bn);
    }
    grid_barrier(nb);

    // ===== phase 2: slow path (uniform early exit) =====
    if ((g_flags[0] | g_flags[1]) == 0) return;

    for (int z = 0; z < 9; z++) {
        if (!flag_ok(md.cfs[z])) continue;
        const float4* __restrict__ src = md.csrc[z];
        uint2* __restrict__ dst = md.cdst[z];
        const int n4 = md.cn4[z];
        for (int i = blockIdx.x * 256 + tid; i < n4; i += nb * 256) {
            float4 v = src[i];
            __half2 h0 = __floats2half2_rn(v.x, v.y);
            __half2 h1 = __floats2half2_rn(v.z, v.w);
            uint2 o;
            o.x = *(uint32_t*)&h0;
            o.y = *(uint32_t*)&h1;
            dst[i] = o;
        }
    }
    grid_barrier(nb);

    const int lane = tid & 31;
    const int wid = tid >> 5;
    const int g = lane >> 2;
    const int t = lane & 3;
    const int wm = wid & 1;
    const int wn = wid >> 1;

    for (int ti = blockIdx.x; ti < 3 * 512; ti += (int)nb) {
        const int z = ti >> 9;
        const int tt = ti & 511;
        if (!flag_ok(md.sfs2[z])) continue;
        const int bn = (tt & 15) * CTAN;
        const int bm = (tt >> 4) * CTAM;

        float c[4][4][4];
        #pragma unroll
        for (int i = 0; i < 4; i++)
            #pragma unroll
            for (int j = 0; j < 4; j++)
                #pragma unroll
                for (int q = 0; q < 4; q++) c[i][j][q] = 0.0f;

        gemm_tile(sb0, tid, bm, bn, md.np2[z], md.A2[z], md.W2[z], md.pfs2[z], c);

        if (md.epi2[z] == 2) {
            const float* __restrict__ m0p = md.mem0;
            __half* __restrict__ aup = md.aup;
            const float* b0 = md.bb0[z];
            const float* b1 = md.bb1[z];
            const float* b2 = md.bb2[z];
            #pragma unroll
            for (int nf = 0; nf < 4; nf++) {
                const int col = bn + wn * 32 + nf * 8 + 2 * t;
                float bs0 = b0[col] + b1[col] + b2[col];
                float bs1 = b0[col + 1] + b1[col + 1] + b2[col + 1];
                #pragma unroll
                for (int mf = 0; mf < 4; mf++) {
                    const int r = bm + wm * 64 + mf * 16 + g;
                    float2 v0 = make_float2(c[mf][nf][0] + bs0, c[mf][nf][1] + bs1);
                    float2 v1 = make_float2(c[mf][nf][2] + bs0, c[mf][nf][3] + bs1);
                    float2 m0 = *(const float2*)(m0p + (size_t)r * DDIM + col);
                    float2 m1 = *(const float2*)(m0p + (size_t)(r + 8) * DDIM + col);
                    __half2 h0 = __floats2half2_rn(sigmoidf_(v0.x) * m0.x,
                                                   sigmoidf_(v0.y) * m0.y);
                    __half2 h1 = __floats2half2_rn(sigmoidf_(v1.x) * m1.x,
                                                   sigmoidf_(v1.y) * m1.y);
                    *(__half2*)(aup + (size_t)r * KDIM + col) = h0;
                    *(__half2*)(aup + (size_t)(r + 8) * KDIM + col) = h1;
                }
            }
        } else {
            float* __restrict__ C = md.C2[z];
            #pragma unroll
            for (int nf = 0; nf < 4; nf++) {
                const int col = bn + wn * 32 + nf * 8 + 2 * t;
                #pragma unroll
                for (int mf = 0; mf < 4; mf++) {
                    const int r = bm + wm * 64 + mf * 16 + g;
                    float2* p0 = (float2*)(C + (size_t)r * DDIM + col);
                    float2* p1 = (float2*)(C + (size_t)(r + 8) * DDIM + col);
                    float2 o0 = *p0, o1 = *p1;
                    o0.x += c[mf][nf][0]; o0.y += c[mf][nf][1];
                    o1.x += c[mf][nf][2]; o1.y += c[mf][nf][3];
                    *p0 = o0;
                    *p1 = o1;
                }
            }
        }
    }
    grid_barrier(nb);

    for (int ti = blockIdx.x; ti < 2 * 512; ti += (int)nb) {
        const int z = ti >> 9;
        const int tt = ti & 511;
        const int bn = (tt & 15) * CTAN;
        const int bm = (tt >> 4) * CTAM;

        if (z == 0) {
            if (g_flags[0] == 0) continue;
            float c[4][4][4];
            #pragma unroll
            for (int i = 0; i < 4; i++)
                #pragma unroll
                for (int j = 0; j < 4; j++)
                    #pragma unroll
                    for (int q = 0; q < 4; q++) c[i][j][q] = 0.0f;
            const __half* Ap[1] = { md.Adec };
            const __half* Wp[1] = { md.Wdec };
            const int pf[1] = { 0 };
            gemm_tile(sb0, tid, bm, bn, 1, Ap, Wp, pf, c);

            #pragma unroll
            for (int nf = 0; nf < 4; nf++) {
                const int col = bn + wn * 32 + nf * 8 + 2 * t;
                const float d0 = md.bdec[col], d1 = md.bdec[col + 1];
                #pragma unroll
                for (int mf = 0; mf < 4; mf++) {
                    const int r = bm + wm * 64 + mf * 16 + g;
                    float2 pa0 = *(const float2*)(md.preA + (size_t)r * DDIM + col);
                    float2 pa1 = *(const float2*)(md.preA + (size_t)(r + 8) * DDIM + col);
                    float2 pb0 = *(const float2*)(md.preB + (size_t)r * DDIM + col);
                    float2 pb1 = *(const float2*)(md.preB + (size_t)(r + 8) * DDIM + col);
                    float2 o0, o1;
                    o0.x = c[mf][nf][0] + d0 + sigmoidf_(pa0.x) * sigmoidf_(pb0.x);
                    o0.y = c[mf][nf][1] + d1 + sigmoidf_(pa0.y) * sigmoidf_(pb0.y);
                    o1.x = c[mf][nf][2] + d0 + sigmoidf_(pa1.x) * sigmoidf_(pb1.x);
                    o1.y = c[mf][nf][3] + d1 + sigmoidf_(pa1.y) * sigmoidf_(pb1.y);
                    *(float2*)(md.outp + (size_t)r * DDIM + col) = o0;
                    *(float2*)(md.outp + (size_t)(r + 8) * DDIM + col) = o1;
                }
            }
        } else {
            if (!(g_flags[1] != 0 && g_flags[0] == 0)) continue;
            #pragma unroll
            for (int nf = 0; nf < 4; nf++) {
                const int col = bn + wn * 32 + nf * 8 + 2 * t;
                const float d0 = md.bdec[col], d1 = md.bdec[col + 1];
                #pragma unroll
                for (int mf = 0; mf < 4; mf++) {
                    const int r = bm + wm * 64 + mf * 16 + g;
                    float2 pa0 = *(const float2*)(md.preA + (size_t)r * DDIM + col);
                    float2 pa1 = *(const float2*)(md.preA + (size_t)(r + 8) * DDIM + col);
                    float2 pb0 = *(const float2*)(md.preB + (size_t)r * DDIM + col);
                    float2 pb1 = *(const float2*)(md.preB + (size_t)(r + 8) * DDIM + col);
                    float2 o0, o1;
                    o0.x = d0 + sigmoidf_(pa0.x) * sigmoidf_(pb0.x);
                    o0.y = d1 + sigmoidf_(pa0.y) * sigmoidf_(pb0.y);
                    o1.x = d0 + sigmoidf_(pa1.x) * sigmoidf_(pb1.x);
                    o1.y = d1 + sigmoidf_(pa1.y) * sigmoidf_(pb1.y);
                    *(float2*)(md.outp + (size_t)r * DDIM + col) = o0;
                    *(float2*)(md.outp + (size_t)(r + 8) * DDIM + col) = o1;
                }
            }
        }
    }
}

// ---------------- host orchestration ----------------
extern "C" void kernel_launch(void* const* d_in, const int* in_sizes, int n_in,
                              void* d_out, int out_size) {
    const float* x              = (const float*)d_in[0];
    const float* out0           = (const float*)d_in[1];
    const float* mem0           = (const float*)d_in[2];
    const float* w_inpgate      = (const float*)d_in[3];
    const float* b_inpgate      = (const float*)d_in[4];
    const float* w_rec_inpgate  = (const float*)d_in[5];
    const float* b_rec_inpgate  = (const float*)d_in[6];
    const float* w_mem_inpgate  = (const float*)d_in[7];
    const float* b_mem_inpgate  = (const float*)d_in[8];
    const float* w_inp          = (const float*)d_in[9];
    const float* b_inp          = (const float*)d_in[10];
    const float* w_rec_inp      = (const float*)d_in[11];
    const float* b_rec_inp      = (const float*)d_in[12];
    const float* w_readgate     = (const float*)d_in[13];
    const float* b_readgate     = (const float*)d_in[14];
    const float* w_rec_readgate = (const float*)d_in[15];
    const float* b_rec_readgate = (const float*)d_in[16];
    const float* w_mem_readgate = (const float*)d_in[17];
    const float* b_mem_readgate = (const float*)d_in[18];
    const float* w_decoder      = (const float*)d_in[19];
    const float* b_decoder      = (const float*)d_in[20];
    float* out = (float*)d_out;

    void *pA, *pB, *pax, *pay, *paz, *pau;
    void *pw0, *pw1, *pw2, *pw3, *pw4, *pw5, *pw6;
    cudaGetSymbolAddress(&pA, g_preA); cudaGetSymbolAddress(&pB, g_preB);
    cudaGetSymbolAddress(&pax, g_ax);  cudaGetSymbolAddress(&pay, g_ay);
    cudaGetSymbolAddress(&paz, g_az);  cudaGetSymbolAddress(&pau, g_au);
    cudaGetSymbolAddress(&pw0, g_w0);  cudaGetSymbolAddress(&pw1, g_w1);
    cudaGetSymbolAddress(&pw2, g_w2);  cudaGetSymbolAddress(&pw3, g_w3);
    cudaGetSymbolAddress(&pw4, g_w4);  cudaGetSymbolAddress(&pw5, g_w5);
    cudaGetSymbolAddress(&pw6, g_w6);
    float* preA = (float*)pA;  float* preB = (float*)pB;
    __half* ax = (__half*)pax; __half* ay = (__half*)pay;
    __half* az = (__half*)paz; __half* au = (__half*)pau;
    __half* w0h = (__half*)pw0; __half* w1h = (__half*)pw1; __half* w2h = (__half*)pw2;
    __half* w3h = (__half*)pw3; __half* w4h = (__half*)pw4; __half* w5h = (__half*)pw5;
    __half* w6h = (__half*)pw6;

    cudaFuncSetAttribute(mega, cudaFuncAttributeMaxDynamicSharedMemorySize, GEMM_SMEM);

    const int nA4 = (BDIM * KDIM) / 4;
    const int nW4 = (DDIM * KDIM) / 4;

    MegaDesc md = {};
    // phase 0
    md.px   = (const float4*)x;         md.pax = (uint2*)ax;
    md.pmem = (const float4*)mem0;      md.pout = (const float4*)out0;
    md.pwi  = (const float4*)w_inp;     md.pw0 = (uint2*)w0h;
    md.pwg  = (const float4*)w_inpgate; md.pw1 = (uint2*)w1h;
    // phase 1
    md.A = ax; md.W0 = w0h; md.W1 = w1h;
    md.preA = preA; md.preB = preB;
    md.bA0 = b_inp;     md.bA1 = b_rec_inp;
    md.bB0 = b_inpgate; md.bB1 = b_mem_inpgate; md.bB2 = b_rec_inpgate;
    md.outp = out; md.bdec = b_decoder;
    // phase 2
    md.csrc[0] = (const float4*)out0;            md.cdst[0] = (uint2*)ay;  md.cn4[0] = nA4; md.cfs[0] = 2;
    md.csrc[1] = (const float4*)mem0;            md.cdst[1] = (uint2*)az;  md.cn4[1] = nA4; md.cfs[1] = 1;
    md.csrc[2] = (const float4*)w_readgate;      md.cdst[2] = (uint2*)w2h; md.cn4[2] = nW4; md.cfs[2] = 1;
    md.csrc[3] = (const float4*)w_rec_inp;       md.cdst[3] = (uint2*)w3h; md.cn4[3] = nW4; md.cfs[3] = 2;
    md.csrc[4] = (const float4*)w_rec_inpgate;   md.cdst[4] = (uint2*)w4h; md.cn4[4] = nW4; md.cfs[4] = 2;
    md.csrc[5] = (const float4*)w_rec_readgate;  md.cdst[5] = (uint2*)w5h; md.cn4[5] = nW4; md.cfs[5] = 3;
    md.csrc[6] = (const float4*)w_mem_inpgate;   md.cdst[6] = (uint2*)w0h; md.cn4[6] = nW4; md.cfs[6] = 1;
    md.csrc[7] = (const float4*)w_mem_readgate;  md.cdst[7] = (uint2*)w1h; md.cn4[7] = nW4; md.cfs[7] = 1;
    md.csrc[8] = (const float4*)w_decoder;       md.cdst[8] = (uint2*)w6h; md.cn4[8] = nW4; md.cfs[8] = 1;
    md.sfs2[0] = 1; md.np2[0] = 3; md.epi2[0] = 2;
    md.A2[0][0] = ax; md.W2[0][0] = w2h; md.pfs2[0][0] = 1;   // x @ w_readgate
    md.A2[0][1] = ay; md.W2[0][1] = w5h; md.pfs2[0][1] = 3;   // out0 @ w_rec_readgate
    md.A2[0][2] = az; md.W2[0][2] = w1h; md.pfs2[0][2] = 1;   // mem0 @ w_mem_readgate
    md.bb0[0] = b_readgate; md.bb1[0] = b_mem_readgate; md.bb2[0] = b_rec_readgate;
    md.sfs2[1] = 2; md.np2[1] = 1; md.epi2[1] = 0;
    md.A2[1][0] = ay; md.W2[1][0] = w3h; md.pfs2[1][0] = 2;
    md.C2[1] = preA;
    md.sfs2[2] = 4; md.np2[2] = 2; md.epi2[2] = 0;
    md.A2[2][0] = ay; md.W2[2][0] = w4h; md.pfs2[2][0] = 2;
    md.A2[2][1] = az; md.W2[2][1] = w0h; md.pfs2[2][1] = 1;
    md.C2[2] = preB;
    md.Adec = au; md.Wdec = w6h;
    md.mem0 = mem0; md.aup = au;

    // ONE persistent launch: prep | barrier | dual GEMM | barrier | slow path
    mega<<<296, 256, GEMM_SMEM>>>(md);
}